// round 1
// baseline (speedup 1.0000x reference)
#include <cuda_runtime.h>

#define VOCAB 100000
#define D     300
#define KW    5
#define L     128
#define NROW  1024
#define LT    124           // valid conv output length

// scratch (device globals; no allocation allowed)
__device__ float d_cwT[KW * D * D];   // [k][c][o]  transposed conv weights
__device__ float d_Wf [KW * D * D];   // [k*D + d][o]  fused (W1 ∘ conv) weights
__device__ float d_biasf[D];          // fused bias

// ---------------- packed f32x2 helpers ----------------
__device__ __forceinline__ unsigned long long pack2(float lo, float hi) {
    unsigned long long r;
    asm("mov.b64 %0, {%1, %2};" : "=l"(r) : "f"(lo), "f"(hi));
    return r;
}
__device__ __forceinline__ void fma2(unsigned long long& acc,
                                     unsigned long long a, unsigned long long b) {
    asm("fma.rn.f32x2 %0, %1, %2, %0;" : "+l"(acc) : "l"(a), "l"(b));
}
__device__ __forceinline__ float lo32(unsigned long long v) {
    return __uint_as_float((unsigned)(v & 0xffffffffull));
}
__device__ __forceinline__ float hi32(unsigned long long v) {
    return __uint_as_float((unsigned)(v >> 32));
}

// ---------------- kernel 1: transpose conv_w + fused bias ----------------
__global__ void prep_kernel(const float* __restrict__ conv_w,
                            const float* __restrict__ conv_b,
                            const float* __restrict__ b1) {
    int idx = blockIdx.x * blockDim.x + threadIdx.x;
    if (idx < KW * D * D) {
        int o = idx % D;
        int c = (idx / D) % D;
        int k = idx / (D * D);
        d_cwT[idx] = conv_w[(o * D + c) * KW + k];   // cwT[k][c][o]
    }
    if (blockIdx.x == 0 && threadIdx.x < D) {
        int o = threadIdx.x;
        float s = conv_b[o];
        const float* cw = conv_w + (size_t)o * D * KW;
        for (int c = 0; c < D; c++) {
            float bc = b1[c];
            #pragma unroll
            for (int k = 0; k < KW; k++) s += bc * cw[c * KW + k];
        }
        d_biasf[o] = s;
    }
}

// ---------------- kernel 2: Wf[k*D+d][o] = sum_c W1[d][c] * cwT[k][c][o] ----------------
#define DG 8
__global__ void fuse_kernel(const float* __restrict__ W1) {
    __shared__ float w1s[DG][D];
    int k  = blockIdx.x / 38;
    int d0 = (blockIdx.x % 38) * DG;
    int tid = threadIdx.x;
    for (int idx = tid; idx < DG * D; idx += blockDim.x) {
        int q = idx / D, c = idx % D;
        w1s[q][c] = (d0 + q < D) ? W1[(size_t)(d0 + q) * D + c] : 0.f;
    }
    __syncthreads();
    int o = tid;
    if (o < D) {
        float acc[DG];
        #pragma unroll
        for (int q = 0; q < DG; q++) acc[q] = 0.f;
        const float* ct = d_cwT + (size_t)k * D * D + o;
        for (int c = 0; c < D; c++) {
            float cw = ct[(size_t)c * D];
            #pragma unroll
            for (int q = 0; q < DG; q++) acc[q] = fmaf(w1s[q][c], cw, acc[q]);
        }
        #pragma unroll
        for (int q = 0; q < DG; q++)
            if (d0 + q < D) d_Wf[(size_t)(k * D + d0 + q) * D + o] = acc[q];
    }
}

// ---------------- kernel 3: fused gather + conv-GEMM + maxpool + MLP ----------------
// SMEM gathered tile gI: pair-interleaved rows: gI[rr][j] = (g[rr][j], g[rr+64][j])
#define GROWS 68
#define GSTR  602           // floats per gI row (2*300 + 2 pad, kills 4-row bank overlap)
#define KC    30            // reduction chunk (j) per stage
#define WSF   (KC * 64)     // 1920 floats per W tile buffer
#define NSTAGE 50           // 5 k * 10 j-chunks

__global__ void __launch_bounds__(256, 1)
main_kernel(const int*   __restrict__ tok,
            const float* __restrict__ mention,
            const float* __restrict__ emb,
            const float* __restrict__ W2, const float* __restrict__ b2,
            const float* __restrict__ W3, const float* __restrict__ b3,
            float* __restrict__ out) {
    extern __shared__ float sm[];
    float* gI   = sm;                    // 68*602 = 40936
    float* ws   = gI + GROWS * GSTR;     // 2*1920 = 3840
    float* conc = ws + 2 * WSF;          // 600 (cnn_out lands in [0,300))
    float* red  = conc + 600;            // 1024 (reduction buf, reused as h)
    int*   stok = (int*)(red + 1024);    // 128

    const int n   = blockIdx.x;
    const int tid = threadIdx.x;
    const int tx  = tid & 15;
    const int ty  = tid >> 4;

    if (tid < L) stok[tid] = tok[n * L + tid];
    // zero the hi-slot pad (rows 128..131 of the logical g)
    for (int idx = tid; idx < 4 * D; idx += 256)
        gI[(64 + idx / D) * GSTR + (idx % D) * 2 + 1] = 0.f;
    __syncthreads();

    // gather emb rows into pair-interleaved SMEM tile
    for (int idx = tid; idx < L * (D / 4); idx += 256) {
        int r = idx / (D / 4);
        int q = idx % (D / 4);
        const float4 v = __ldg(((const float4*)(emb + (size_t)stok[r] * D)) + q);
        float vv[4] = {v.x, v.y, v.z, v.w};
        int j0 = q * 4;
        #pragma unroll
        for (int u = 0; u < 4; u++) {
            int j = j0 + u;
            if (r < GROWS) gI[r * GSTR + 2 * j]            = vv[u];
            if (r >= 64)   gI[(r - 64) * GSTR + 2 * j + 1] = vv[u];
        }
    }
    __syncthreads();

    // ---- conv GEMM with running max, o-tiles of 64 ----
    for (int ot = 0; ot < 5; ot++) {
        const int ob = ot * 64;

        unsigned long long acc[4][4];
        #pragma unroll
        for (int i = 0; i < 4; i++)
            #pragma unroll
            for (int q = 0; q < 4; q++) acc[i][q] = 0ull;

        // stage 0 load (Wf row base for stage s is simply s*30)
        #pragma unroll
        for (int u = 0; u < 8; u++) {
            int idx = tid + u * 256;
            if (idx < WSF) {
                int o = ob + (idx & 63);
                ws[idx] = (o < D) ? __ldg(&d_Wf[(size_t)(idx >> 6) * D + o]) : 0.f;
            }
        }
        __syncthreads();

        for (int s = 0; s < NSTAGE; s++) {
            // prefetch next stage into registers (latency hidden by compute)
            float pf[8];
            if (s + 1 < NSTAGE) {
                const int r0 = (s + 1) * KC;
                #pragma unroll
                for (int u = 0; u < 8; u++) {
                    int idx = tid + u * 256;
                    float v = 0.f;
                    if (idx < WSF) {
                        int o = ob + (idx & 63);
                        if (o < D) v = __ldg(&d_Wf[(size_t)(r0 + (idx >> 6)) * D + o]);
                    }
                    pf[u] = v;
                }
            }

            const float* wb = ws + (s & 1) * WSF + tx * 4;
            const int k = s / 10;
            const float* gbase = gI + (ty * 4 + k) * GSTR + 2 * ((s % 10) * KC);

            #pragma unroll
            for (int jj = 0; jj < KC; jj++) {
                float4 w = *(const float4*)(wb + jj * 64);
                unsigned long long b0 = pack2(w.x, w.x);
                unsigned long long b1p = pack2(w.y, w.y);
                unsigned long long b2p = pack2(w.z, w.z);
                unsigned long long b3p = pack2(w.w, w.w);
                #pragma unroll
                for (int i = 0; i < 4; i++) {
                    unsigned long long a =
                        *(const unsigned long long*)(gbase + i * GSTR + 2 * jj);
                    fma2(acc[i][0], a, b0);
                    fma2(acc[i][1], a, b1p);
                    fma2(acc[i][2], a, b2p);
                    fma2(acc[i][3], a, b3p);
                }
            }

            if (s + 1 < NSTAGE) {
                float* wo = ws + ((s + 1) & 1) * WSF;
                #pragma unroll
                for (int u = 0; u < 8; u++) {
                    int idx = tid + u * 256;
                    if (idx < WSF) wo[idx] = pf[u];
                }
            }
            __syncthreads();
        }

        // max over t within thread, then across ty groups
        float pm[4];
        #pragma unroll
        for (int q = 0; q < 4; q++) {
            float m = -3.4e38f;
            #pragma unroll
            for (int i = 0; i < 4; i++) {
                m = fmaxf(m, lo32(acc[i][q]));            // t = ty*4+i (< 64, always valid)
                if (ty * 4 + i + 64 < LT)                 // t = ty*4+i+64
                    m = fmaxf(m, hi32(acc[i][q]));
            }
            pm[q] = m;
        }
        *(float4*)(red + ty * 64 + tx * 4) = make_float4(pm[0], pm[1], pm[2], pm[3]);
        __syncthreads();
        if (tid < 64) {
            float m = red[tid];
            #pragma unroll
            for (int yy = 1; yy < 16; yy++) m = fmaxf(m, red[yy * 64 + tid]);
            int o = ob + tid;
            if (o < D) conc[o] = m + d_biasf[o];
        }
        __syncthreads();
    }

    // ---- epilogue: concat, 600x300 tanh GEMV, 300x300 GEMV ----
    for (int idx = tid; idx < D; idx += 256)
        conc[D + idx] = mention[(size_t)n * D + idx];
    __syncthreads();

    float* h = red;
    for (int o = tid; o < D; o += 256) {
        float s = b2[o];
        for (int j = 0; j < 2 * D; j++) s = fmaf(conc[j], W2[(size_t)j * D + o], s);
        h[o] = tanhf(s);
    }
    __syncthreads();
    for (int o = tid; o < D; o += 256) {
        float s = b3[o];
        for (int j = 0; j < D; j++) s = fmaf(h[j], W3[(size_t)j * D + o], s);
        out[(size_t)n * D + o] = s;
    }
}

// ---------------- launch ----------------
extern "C" void kernel_launch(void* const* d_in, const int* in_sizes, int n_in,
                              void* d_out, int out_size) {
    const int*   tok     = (const int*)  d_in[0];
    const float* mention = (const float*)d_in[1];
    const float* emb     = (const float*)d_in[2];
    const float* W1      = (const float*)d_in[3];
    const float* b1      = (const float*)d_in[4];
    const float* conv_w  = (const float*)d_in[5];
    const float* conv_b  = (const float*)d_in[6];
    const float* W2      = (const float*)d_in[7];
    const float* b2      = (const float*)d_in[8];
    const float* W3      = (const float*)d_in[9];
    const float* b3      = (const float*)d_in[10];
    float* out = (float*)d_out;

    const int smem_bytes = (GROWS * GSTR + 2 * WSF + 600 + 1024 + 128) * 4; // 186112
    cudaFuncSetAttribute(main_kernel,
                         cudaFuncAttributeMaxDynamicSharedMemorySize, smem_bytes);

    prep_kernel<<<(KW * D * D + 255) / 256, 256>>>(conv_w, conv_b, b1);
    fuse_kernel<<<KW * 38, 320>>>(W1);
    main_kernel<<<NROW, 256, smem_bytes>>>(tok, mention, emb, W2, b2, W3, b3, out);
}

// round 2
// speedup vs baseline: 1.0009x; 1.0009x over previous
#include <cuda_runtime.h>

#define VOCAB 100000
#define D     300
#define KW    5
#define L     128
#define NROW  1024
#define LT    124           // valid conv output length

// scratch (device globals; no allocation allowed)
__device__ float d_cwT[KW * D * D];   // [k][c][o]  transposed conv weights
__device__ float d_Wf [KW * D * D];   // [k*D + d][o]  fused (W1 ∘ conv) weights
__device__ float d_biasf[D];          // fused bias

// ---------------- packed f32x2 helpers ----------------
__device__ __forceinline__ unsigned long long pack2(float lo, float hi) {
    unsigned long long r;
    asm("mov.b64 %0, {%1, %2};" : "=l"(r) : "f"(lo), "f"(hi));
    return r;
}
__device__ __forceinline__ void fma2(unsigned long long& acc,
                                     unsigned long long a, unsigned long long b) {
    asm("fma.rn.f32x2 %0, %1, %2, %0;" : "+l"(acc) : "l"(a), "l"(b));
}
__device__ __forceinline__ float lo32(unsigned long long v) {
    return __uint_as_float((unsigned)(v & 0xffffffffull));
}
__device__ __forceinline__ float hi32(unsigned long long v) {
    return __uint_as_float((unsigned)(v >> 32));
}

// ---------------- kernel 1: transpose conv_w + fused bias ----------------
__global__ void prep_kernel(const float* __restrict__ conv_w,
                            const float* __restrict__ conv_b,
                            const float* __restrict__ b1) {
    int idx = blockIdx.x * blockDim.x + threadIdx.x;
    if (idx < KW * D * D) {
        int o = idx % D;
        int c = (idx / D) % D;
        int k = idx / (D * D);
        d_cwT[idx] = conv_w[(o * D + c) * KW + k];   // cwT[k][c][o]
    }
    if (blockIdx.x == 0 && threadIdx.x < D) {
        int o = threadIdx.x;
        float s = conv_b[o];
        const float* cw = conv_w + (size_t)o * D * KW;
        for (int c = 0; c < D; c++) {
            float bc = b1[c];
            #pragma unroll
            for (int k = 0; k < KW; k++) s += bc * cw[c * KW + k];
        }
        d_biasf[o] = s;
    }
}

// ---------------- kernel 2: Wf[k*D+d][o] = sum_c W1[d][c] * cwT[k][c][o] ----------------
#define DG 8
__global__ void fuse_kernel(const float* __restrict__ W1) {
    __shared__ float w1s[DG][D];
    int k  = blockIdx.x / 38;
    int d0 = (blockIdx.x % 38) * DG;
    int tid = threadIdx.x;
    for (int idx = tid; idx < DG * D; idx += blockDim.x) {
        int q = idx / D, c = idx % D;
        w1s[q][c] = (d0 + q < D) ? W1[(size_t)(d0 + q) * D + c] : 0.f;
    }
    __syncthreads();
    int o = tid;
    if (o < D) {
        float acc[DG];
        #pragma unroll
        for (int q = 0; q < DG; q++) acc[q] = 0.f;
        const float* ct = d_cwT + (size_t)k * D * D + o;
        for (int c = 0; c < D; c++) {
            float cw = ct[(size_t)c * D];
            #pragma unroll
            for (int q = 0; q < DG; q++) acc[q] = fmaf(w1s[q][c], cw, acc[q]);
        }
        #pragma unroll
        for (int q = 0; q < DG; q++)
            if (d0 + q < D) d_Wf[(size_t)(k * D + d0 + q) * D + o] = acc[q];
    }
}

// ---------------- kernel 3: fused gather + conv-GEMM + maxpool + MLP ----------------
// SMEM gathered tile gI: pair-interleaved rows: gI[rr][j] = (g[rr][j], g[rr+64][j])
#define GROWS 68
#define GSTR  602           // floats per gI row (2*300 + 2 pad, kills 4-row bank overlap)
#define KC    30            // reduction chunk (j) per stage
#define WSF   (KC * 64)     // 1920 floats per W tile buffer
#define NSTAGE 50           // 5 k * 10 j-chunks

__global__ void __launch_bounds__(256, 1)
main_kernel(const int*   __restrict__ tok,
            const float* __restrict__ mention,
            const float* __restrict__ emb,
            const float* __restrict__ W2, const float* __restrict__ b2,
            const float* __restrict__ W3, const float* __restrict__ b3,
            float* __restrict__ out) {
    extern __shared__ float sm[];
    float* gI   = sm;                    // 68*602 = 40936
    float* ws   = gI + GROWS * GSTR;     // 2*1920 = 3840
    float* conc = ws + 2 * WSF;          // 600 (cnn_out lands in [0,300))
    float* red  = conc + 600;            // 1024 (reduction buf, reused as h)
    int*   stok = (int*)(red + 1024);    // 128

    const int n   = blockIdx.x;
    const int tid = threadIdx.x;
    const int tx  = tid & 15;
    const int ty  = tid >> 4;

    if (tid < L) stok[tid] = tok[n * L + tid];
    // zero the hi-slot pad (rows 128..131 of the logical g)
    for (int idx = tid; idx < 4 * D; idx += 256)
        gI[(64 + idx / D) * GSTR + (idx % D) * 2 + 1] = 0.f;
    __syncthreads();

    // gather emb rows into pair-interleaved SMEM tile
    for (int idx = tid; idx < L * (D / 4); idx += 256) {
        int r = idx / (D / 4);
        int q = idx % (D / 4);
        const float4 v = __ldg(((const float4*)(emb + (size_t)stok[r] * D)) + q);
        float vv[4] = {v.x, v.y, v.z, v.w};
        int j0 = q * 4;
        #pragma unroll
        for (int u = 0; u < 4; u++) {
            int j = j0 + u;
            if (r < GROWS) gI[r * GSTR + 2 * j]            = vv[u];
            if (r >= 64)   gI[(r - 64) * GSTR + 2 * j + 1] = vv[u];
        }
    }
    __syncthreads();

    // ---- conv GEMM with running max, o-tiles of 64 ----
    for (int ot = 0; ot < 5; ot++) {
        const int ob = ot * 64;

        unsigned long long acc[4][4];
        #pragma unroll
        for (int i = 0; i < 4; i++)
            #pragma unroll
            for (int q = 0; q < 4; q++) acc[i][q] = 0ull;

        // stage 0 load (Wf row base for stage s is simply s*30)
        #pragma unroll
        for (int u = 0; u < 8; u++) {
            int idx = tid + u * 256;
            if (idx < WSF) {
                int o = ob + (idx & 63);
                ws[idx] = (o < D) ? __ldg(&d_Wf[(size_t)(idx >> 6) * D + o]) : 0.f;
            }
        }
        __syncthreads();

        for (int s = 0; s < NSTAGE; s++) {
            // prefetch next stage into registers (latency hidden by compute)
            float pf[8];
            if (s + 1 < NSTAGE) {
                const int r0 = (s + 1) * KC;
                #pragma unroll
                for (int u = 0; u < 8; u++) {
                    int idx = tid + u * 256;
                    float v = 0.f;
                    if (idx < WSF) {
                        int o = ob + (idx & 63);
                        if (o < D) v = __ldg(&d_Wf[(size_t)(r0 + (idx >> 6)) * D + o]);
                    }
                    pf[u] = v;
                }
            }

            const float* wb = ws + (s & 1) * WSF + tx * 4;
            const int k = s / 10;
            const float* gbase = gI + (ty * 4 + k) * GSTR + 2 * ((s % 10) * KC);

            #pragma unroll
            for (int jj = 0; jj < KC; jj++) {
                float4 w = *(const float4*)(wb + jj * 64);
                unsigned long long b0 = pack2(w.x, w.x);
                unsigned long long b1p = pack2(w.y, w.y);
                unsigned long long b2p = pack2(w.z, w.z);
                unsigned long long b3p = pack2(w.w, w.w);
                #pragma unroll
                for (int i = 0; i < 4; i++) {
                    unsigned long long a =
                        *(const unsigned long long*)(gbase + i * GSTR + 2 * jj);
                    fma2(acc[i][0], a, b0);
                    fma2(acc[i][1], a, b1p);
                    fma2(acc[i][2], a, b2p);
                    fma2(acc[i][3], a, b3p);
                }
            }

            if (s + 1 < NSTAGE) {
                float* wo = ws + ((s + 1) & 1) * WSF;
                #pragma unroll
                for (int u = 0; u < 8; u++) {
                    int idx = tid + u * 256;
                    if (idx < WSF) wo[idx] = pf[u];
                }
            }
            __syncthreads();
        }

        // max over t within thread, then across ty groups
        float pm[4];
        #pragma unroll
        for (int q = 0; q < 4; q++) {
            float m = -3.4e38f;
            #pragma unroll
            for (int i = 0; i < 4; i++) {
                m = fmaxf(m, lo32(acc[i][q]));            // t = ty*4+i (< 64, always valid)
                if (ty * 4 + i + 64 < LT)                 // t = ty*4+i+64
                    m = fmaxf(m, hi32(acc[i][q]));
            }
            pm[q] = m;
        }
        *(float4*)(red + ty * 64 + tx * 4) = make_float4(pm[0], pm[1], pm[2], pm[3]);
        __syncthreads();
        if (tid < 64) {
            float m = red[tid];
            #pragma unroll
            for (int yy = 1; yy < 16; yy++) m = fmaxf(m, red[yy * 64 + tid]);
            int o = ob + tid;
            if (o < D) conc[o] = m + d_biasf[o];
        }
        __syncthreads();
    }

    // ---- epilogue: concat, 600x300 tanh GEMV, 300x300 GEMV ----
    for (int idx = tid; idx < D; idx += 256)
        conc[D + idx] = mention[(size_t)n * D + idx];
    __syncthreads();

    float* h = red;
    for (int o = tid; o < D; o += 256) {
        float s = b2[o];
        for (int j = 0; j < 2 * D; j++) s = fmaf(conc[j], W2[(size_t)j * D + o], s);
        h[o] = tanhf(s);
    }
    __syncthreads();
    for (int o = tid; o < D; o += 256) {
        float s = b3[o];
        for (int j = 0; j < D; j++) s = fmaf(h[j], W3[(size_t)j * D + o], s);
        out[(size_t)n * D + o] = s;
    }
}

// ---------------- launch ----------------
extern "C" void kernel_launch(void* const* d_in, const int* in_sizes, int n_in,
                              void* d_out, int out_size) {
    const int*   tok     = (const int*)  d_in[0];
    const float* mention = (const float*)d_in[1];
    const float* emb     = (const float*)d_in[2];
    const float* W1      = (const float*)d_in[3];
    const float* b1      = (const float*)d_in[4];
    const float* conv_w  = (const float*)d_in[5];
    const float* conv_b  = (const float*)d_in[6];
    const float* W2      = (const float*)d_in[7];
    const float* b2      = (const float*)d_in[8];
    const float* W3      = (const float*)d_in[9];
    const float* b3      = (const float*)d_in[10];
    float* out = (float*)d_out;

    const int smem_bytes = (GROWS * GSTR + 2 * WSF + 600 + 1024 + 128) * 4; // 186112
    cudaFuncSetAttribute(main_kernel,
                         cudaFuncAttributeMaxDynamicSharedMemorySize, smem_bytes);

    prep_kernel<<<(KW * D * D + 255) / 256, 256>>>(conv_w, conv_b, b1);
    fuse_kernel<<<KW * 38, 320>>>(W1);
    main_kernel<<<NROW, 256, smem_bytes>>>(tok, mention, emb, W2, b2, W3, b3, out);
}